// round 1
// baseline (speedup 1.0000x reference)
#include <cuda_runtime.h>
#include <cstdint>

// Problem constants (fixed by setup_inputs)
#define L1TOK   9360
#define DIMM    5120
#define KVD     1536
#define NHEADS  40
#define HDIM    128
#define LATOK   96
#define NFRAMES 6
#define HWTOK   1560

// Scratch (device globals: allocation-free)
__device__ float g_q[(size_t)L1TOK * DIMM];
__device__ float g_k[(size_t)LATOK * DIMM];
__device__ float g_v[(size_t)LATOK * DIMM];
__device__ float g_o[(size_t)L1TOK * DIMM];

// ---------------------------------------------------------------------------
// TF32 helpers
// ---------------------------------------------------------------------------
__device__ __forceinline__ uint32_t f2tf32(float x) {
    uint32_t u;
    asm("cvt.rna.tf32.f32 %0, %1;" : "=r"(u) : "f"(x));
    return u;
}

__device__ __forceinline__ void mma_tf32(float* c, const uint32_t* a, const uint32_t* b) {
    asm volatile(
        "mma.sync.aligned.m16n8k8.row.col.f32.tf32.tf32.f32 "
        "{%0,%1,%2,%3}, {%4,%5,%6,%7}, {%8,%9}, {%0,%1,%2,%3};\n"
        : "+f"(c[0]), "+f"(c[1]), "+f"(c[2]), "+f"(c[3])
        : "r"(a[0]), "r"(a[1]), "r"(a[2]), "r"(a[3]),
          "r"(b[0]), "r"(b[1]));
}

// ---------------------------------------------------------------------------
// GEMM: C[M,N] = A[M,K] @ B[N,K]^T + bias[N]
// A row-major (M,K), B row-major (N,K)  -> mma row.col
// Tile: BM=128, BN=128, BK=32; 256 threads, 8 warps (2m x 4n), warp = 64x32
// ---------------------------------------------------------------------------
#define BM 128
#define BN 128
#define BKT 32
#define SROW 36   // BK + 4 pad (floats)

__global__ void __launch_bounds__(256, 1)
gemm_tf32_kernel(const float* __restrict__ A, const float* __restrict__ B,
                 const float* __restrict__ bias, float* __restrict__ C,
                 int M, int N, int K)
{
    extern __shared__ float smem[];
    float* sA = smem;                 // [2][BM][SROW]
    float* sB = smem + 2 * BM * SROW; // [2][BN][SROW]

    const int t    = threadIdx.x;
    const int warp = t >> 5;
    const int lane = t & 31;
    const int wm   = warp >> 2;  // 0..1  (64 rows each)
    const int wn   = warp & 3;   // 0..3  (32 cols each)
    const int g    = lane >> 2;  // groupID
    const int tg   = lane & 3;   // thread-in-group

    const int row0_blk = blockIdx.y * BM;
    const int col0_blk = blockIdx.x * BN;

    float acc[4][4][4];
    #pragma unroll
    for (int i = 0; i < 4; i++)
        #pragma unroll
        for (int j = 0; j < 4; j++)
            #pragma unroll
            for (int r = 0; r < 4; r++) acc[i][j][r] = 0.f;

    float4 regA[4], regB[4];

    const int KT = K / BKT;

    auto LDG = [&](int kt) {
        const int k0 = kt * BKT;
        #pragma unroll
        for (int i = 0; i < 4; i++) {
            int id = t + i * 256;
            int r  = id >> 3;
            int c4 = id & 7;
            int ga = row0_blk + r;
            if (ga < M) regA[i] = *(const float4*)(A + (size_t)ga * K + k0 + c4 * 4);
            else        regA[i] = make_float4(0.f, 0.f, 0.f, 0.f);
            int gb = col0_blk + r;  // N is always a multiple of 128 here
            regB[i] = *(const float4*)(B + (size_t)gb * K + k0 + c4 * 4);
        }
    };

    auto STS = [&](int buf) {
        float* dA = sA + buf * BM * SROW;
        float* dB = sB + buf * BN * SROW;
        #pragma unroll
        for (int i = 0; i < 4; i++) {
            int id = t + i * 256;
            int r  = id >> 3;
            int c4 = id & 7;
            uint4 ua;
            ua.x = f2tf32(regA[i].x); ua.y = f2tf32(regA[i].y);
            ua.z = f2tf32(regA[i].z); ua.w = f2tf32(regA[i].w);
            *(uint4*)(dA + r * SROW + c4 * 4) = ua;
            uint4 ub;
            ub.x = f2tf32(regB[i].x); ub.y = f2tf32(regB[i].y);
            ub.z = f2tf32(regB[i].z); ub.w = f2tf32(regB[i].w);
            *(uint4*)(dB + r * SROW + c4 * 4) = ub;
        }
    };

    LDG(0);
    STS(0);
    __syncthreads();

    int buf = 0;
    for (int kt = 0; kt < KT; ++kt) {
        if (kt + 1 < KT) LDG(kt + 1);

        const uint32_t* uA = (const uint32_t*)(sA + buf * BM * SROW);
        const uint32_t* uB = (const uint32_t*)(sB + buf * BN * SROW);

        #pragma unroll
        for (int ks = 0; ks < 4; ++ks) {
            const int kk = ks * 8;
            uint32_t af[4][4], bf[4][2];
            #pragma unroll
            for (int mt = 0; mt < 4; ++mt) {
                int r = wm * 64 + mt * 16 + g;
                af[mt][0] = uA[(r    ) * SROW + kk + tg    ];
                af[mt][1] = uA[(r + 8) * SROW + kk + tg    ];
                af[mt][2] = uA[(r    ) * SROW + kk + tg + 4];
                af[mt][3] = uA[(r + 8) * SROW + kk + tg + 4];
            }
            #pragma unroll
            for (int nt = 0; nt < 4; ++nt) {
                int n = wn * 32 + nt * 8 + g;
                bf[nt][0] = uB[n * SROW + kk + tg    ];
                bf[nt][1] = uB[n * SROW + kk + tg + 4];
            }
            #pragma unroll
            for (int mt = 0; mt < 4; ++mt)
                #pragma unroll
                for (int nt = 0; nt < 4; ++nt)
                    mma_tf32(acc[mt][nt], af[mt], bf[nt]);
        }

        if (kt + 1 < KT) STS(buf ^ 1);
        __syncthreads();
        buf ^= 1;
    }

    // Epilogue: add bias, guarded row writes
    #pragma unroll
    for (int mt = 0; mt < 4; ++mt) {
        int r0 = row0_blk + wm * 64 + mt * 16 + g;
        #pragma unroll
        for (int nt = 0; nt < 4; ++nt) {
            int c0 = col0_blk + wn * 32 + nt * 8 + tg * 2;
            float b0v = bias[c0];
            float b1v = bias[c0 + 1];
            if (r0 < M) {
                C[(size_t)r0 * N + c0    ] = acc[mt][nt][0] + b0v;
                C[(size_t)r0 * N + c0 + 1] = acc[mt][nt][1] + b1v;
            }
            if (r0 + 8 < M) {
                C[(size_t)(r0 + 8) * N + c0    ] = acc[mt][nt][2] + b0v;
                C[(size_t)(r0 + 8) * N + c0 + 1] = acc[mt][nt][3] + b1v;
            }
        }
    }
}

// ---------------------------------------------------------------------------
// RMSNorm in-place over rows of length DIMM (5120). One block of 256 per row.
// ---------------------------------------------------------------------------
__global__ void __launch_bounds__(256)
rmsnorm_kernel(float* __restrict__ buf, const float* __restrict__ gvec)
{
    const int row = blockIdx.x;
    const int t = threadIdx.x;
    const int lane = t & 31;
    const int warp = t >> 5;

    float4* p4 = (float4*)(buf + (size_t)row * DIMM);
    const float4* g4 = (const float4*)gvec;

    float4 v[5];
    float ss = 0.f;
    #pragma unroll
    for (int i = 0; i < 5; i++) {
        v[i] = p4[t + i * 256];
        ss += v[i].x * v[i].x + v[i].y * v[i].y + v[i].z * v[i].z + v[i].w * v[i].w;
    }

    #pragma unroll
    for (int off = 16; off > 0; off >>= 1)
        ss += __shfl_xor_sync(0xffffffffu, ss, off);

    __shared__ float red[8];
    __shared__ float stot;
    if (lane == 0) red[warp] = ss;
    __syncthreads();
    if (t < 8) {
        float tot = red[t];
        #pragma unroll
        for (int off = 4; off > 0; off >>= 1)
            tot += __shfl_xor_sync(0x000000ffu, tot, off);
        if (t == 0) stot = tot;
    }
    __syncthreads();

    const float inv = rsqrtf(stot / (float)DIMM + 1e-6f);

    #pragma unroll
    for (int i = 0; i < 5; i++) {
        float4 gv = g4[t + i * 256];
        float4 o;
        o.x = v[i].x * inv * gv.x;
        o.y = v[i].y * inv * gv.y;
        o.z = v[i].z * inv * gv.z;
        o.w = v[i].w * inv * gv.w;
        p4[t + i * 256] = o;
    }
}

// ---------------------------------------------------------------------------
// Attention: per (frame, head): softmax(Q Kᵀ * scale) V, 16 keys per frame.
// grid.x = frame*NHEADS + head, grid.y = chunk of 16 q-rows; 128 threads.
// ---------------------------------------------------------------------------
#define SKPAD 132

__global__ void __launch_bounds__(128)
attn_kernel(const float* __restrict__ q, const float* __restrict__ k,
            const float* __restrict__ v, float* __restrict__ o)
{
    const int fh = blockIdx.x;
    const int f  = fh / NHEADS;
    const int h  = fh % NHEADS;

    __shared__ float sk[16][SKPAD];
    __shared__ float sv[16][SKPAD];

    const int t = threadIdx.x;
    #pragma unroll
    for (int i = 0; i < 4; i++) {
        int id = t + i * 128;   // float4 id within 16x128
        int j  = id >> 5;       // key row 0..15
        int c4 = id & 31;       // float4 col
        size_t goff = ((size_t)(f * 16 + j)) * DIMM + h * HDIM + c4 * 4;
        float4 kv = *(const float4*)(k + goff);
        *(float4*)(&sk[j][c4 * 4]) = kv;
        float4 vv = *(const float4*)(v + goff);
        *(float4*)(&sv[j][c4 * 4]) = vv;
    }
    __syncthreads();

    const int warp = t >> 5;
    const int lane = t & 31;
    const float scale = 0.08838834764831844f;  // 1/sqrt(128)

    #pragma unroll
    for (int rr = 0; rr < 4; ++rr) {
        const int pos = blockIdx.y * 16 + warp * 4 + rr;
        if (pos >= HWTOK) break;  // uniform across warp

        const float4* q4 = (const float4*)(q + ((size_t)(f * HWTOK + pos)) * DIMM + h * HDIM);

        float logit = -1e30f;
        if (lane < 16) {
            float s = 0.f;
            #pragma unroll
            for (int c = 0; c < 32; c++) {
                float4 a = q4[c];
                float4 b = *(const float4*)(&sk[lane][c * 4]);
                s += a.x * b.x + a.y * b.y + a.z * b.z + a.w * b.w;
            }
            logit = s * scale;
        }

        // softmax over 16 lanes
        float m = logit;
        #pragma unroll
        for (int off = 8; off > 0; off >>= 1)
            m = fmaxf(m, __shfl_xor_sync(0xffffffffu, m, off, 16));
        float e = (lane < 16) ? expf(logit - m) : 0.f;
        float ssum = e;
        #pragma unroll
        for (int off = 8; off > 0; off >>= 1)
            ssum += __shfl_xor_sync(0xffffffffu, ssum, off, 16);
        float att = (lane < 16) ? (e / ssum) : 0.f;

        // o[d] = sum_j att_j * v[j][d]; lane owns 4 consecutive d's
        float4 oacc = make_float4(0.f, 0.f, 0.f, 0.f);
        #pragma unroll
        for (int j = 0; j < 16; j++) {
            float aj = __shfl_sync(0xffffffffu, att, j);
            float4 vv = *(const float4*)(&sv[j][lane * 4]);
            oacc.x += aj * vv.x;
            oacc.y += aj * vv.y;
            oacc.z += aj * vv.z;
            oacc.w += aj * vv.w;
        }
        *(float4*)(o + ((size_t)(f * HWTOK + pos)) * DIMM + h * HDIM + lane * 4) = oacc;
    }
}

// ---------------------------------------------------------------------------
// Launcher
// ---------------------------------------------------------------------------
extern "C" void kernel_launch(void* const* d_in, const int* in_sizes, int n_in,
                              void* d_out, int out_size)
{
    const float* x   = (const float*)d_in[0];
    const float* ctx = (const float*)d_in[1];
    // d_in[2..5]: context_lens, grid_sizes, freqs, audio_seq_len (unused; shapes fixed)
    const float* Wq  = (const float*)d_in[6];
    const float* bq  = (const float*)d_in[7];
    const float* Wk  = (const float*)d_in[8];
    const float* bk  = (const float*)d_in[9];
    const float* Wv  = (const float*)d_in[10];
    const float* bv  = (const float*)d_in[11];
    const float* Wo  = (const float*)d_in[12];
    const float* bo  = (const float*)d_in[13];
    const float* gq  = (const float*)d_in[14];
    const float* gk  = (const float*)d_in[15];
    float* out = (float*)d_out;

    float *qb, *kb, *vb, *ob;
    cudaGetSymbolAddress((void**)&qb, g_q);
    cudaGetSymbolAddress((void**)&kb, g_k);
    cudaGetSymbolAddress((void**)&vb, g_v);
    cudaGetSymbolAddress((void**)&ob, g_o);

    const int smem_bytes = 2 * (BM * SROW + BN * SROW) * (int)sizeof(float); // 73728
    cudaFuncSetAttribute(gemm_tf32_kernel, cudaFuncAttributeMaxDynamicSharedMemorySize, smem_bytes);

    dim3 blk(256);

    // Q projection: 9360x5120 = x @ Wq^T + bq
    {
        dim3 grid(DIMM / BN, (L1TOK + BM - 1) / BM);
        gemm_tf32_kernel<<<grid, blk, smem_bytes>>>(x, Wq, bq, qb, L1TOK, DIMM, DIMM);
    }
    // K projection: 96x5120 = ctx @ Wk^T + bk
    {
        dim3 grid(DIMM / BN, 1);
        gemm_tf32_kernel<<<grid, blk, smem_bytes>>>(ctx, Wk, bk, kb, LATOK, DIMM, KVD);
    }
    // V projection: 96x5120 = ctx @ Wv^T + bv
    {
        dim3 grid(DIMM / BN, 1);
        gemm_tf32_kernel<<<grid, blk, smem_bytes>>>(ctx, Wv, bv, vb, LATOK, DIMM, KVD);
    }

    // RMSNorm q and k (in place)
    rmsnorm_kernel<<<L1TOK, 256>>>(qb, gq);
    rmsnorm_kernel<<<LATOK, 256>>>(kb, gk);

    // Attention
    {
        dim3 grid(NFRAMES * NHEADS, (HWTOK + 15) / 16);
        attn_kernel<<<grid, 128>>>(qb, kb, vb, ob);
    }

    // Output projection: out = o @ Wo^T + bo
    {
        dim3 grid(DIMM / BN, (L1TOK + BM - 1) / BM);
        gemm_tf32_kernel<<<grid, blk, smem_bytes>>>(ob, Wo, bo, out, L1TOK, DIMM, DIMM);
    }
}

// round 2
// speedup vs baseline: 1.0004x; 1.0004x over previous
#include <cuda_runtime.h>
#include <cstdint>

// Problem constants (fixed by setup_inputs)
#define L1TOK   9360
#define DIMM    5120
#define KVD     1536
#define NHEADS  40
#define HDIM    128
#define LATOK   96
#define NFRAMES 6
#define HWTOK   1560

// Scratch (device globals: allocation-free)
__device__ float g_q[(size_t)L1TOK * DIMM];
__device__ float g_k[(size_t)LATOK * DIMM];
__device__ float g_v[(size_t)LATOK * DIMM];
__device__ float g_o[(size_t)L1TOK * DIMM];

// ---------------------------------------------------------------------------
// TF32 helpers
// ---------------------------------------------------------------------------
__device__ __forceinline__ uint32_t f2tf32(float x) {
    uint32_t u;
    asm("cvt.rna.tf32.f32 %0, %1;" : "=r"(u) : "f"(x));
    return u;
}

__device__ __forceinline__ void mma_tf32(float* c, const uint32_t* a, const uint32_t* b) {
    asm volatile(
        "mma.sync.aligned.m16n8k8.row.col.f32.tf32.tf32.f32 "
        "{%0,%1,%2,%3}, {%4,%5,%6,%7}, {%8,%9}, {%0,%1,%2,%3};\n"
        : "+f"(c[0]), "+f"(c[1]), "+f"(c[2]), "+f"(c[3])
        : "r"(a[0]), "r"(a[1]), "r"(a[2]), "r"(a[3]),
          "r"(b[0]), "r"(b[1]));
}

// ---------------------------------------------------------------------------
// GEMM: C[M,N] = A[M,K] @ B[N,K]^T + bias[N]
// A row-major (M,K), B row-major (N,K)  -> mma row.col
// Tile: BM=128, BN=128, BK=32; 256 threads, 8 warps (2m x 4n), warp = 64x32
// ---------------------------------------------------------------------------
#define BM 128
#define BN 128
#define BKT 32
#define SROW 36   // BK + 4 pad (floats)

__global__ void __launch_bounds__(256, 1)
gemm_tf32_kernel(const float* __restrict__ A, const float* __restrict__ B,
                 const float* __restrict__ bias, float* __restrict__ C,
                 int M, int N, int K)
{
    extern __shared__ float smem[];
    float* sA = smem;                 // [2][BM][SROW]
    float* sB = smem + 2 * BM * SROW; // [2][BN][SROW]

    const int t    = threadIdx.x;
    const int warp = t >> 5;
    const int lane = t & 31;
    const int wm   = warp >> 2;  // 0..1  (64 rows each)
    const int wn   = warp & 3;   // 0..3  (32 cols each)
    const int g    = lane >> 2;  // groupID
    const int tg   = lane & 3;   // thread-in-group

    const int row0_blk = blockIdx.y * BM;
    const int col0_blk = blockIdx.x * BN;

    float acc[4][4][4];
    #pragma unroll
    for (int i = 0; i < 4; i++)
        #pragma unroll
        for (int j = 0; j < 4; j++)
            #pragma unroll
            for (int r = 0; r < 4; r++) acc[i][j][r] = 0.f;

    float4 regA[4], regB[4];

    const int KT = K / BKT;

    auto LDG = [&](int kt) {
        const int k0 = kt * BKT;
        #pragma unroll
        for (int i = 0; i < 4; i++) {
            int id = t + i * 256;
            int r  = id >> 3;
            int c4 = id & 7;
            int ga = row0_blk + r;
            if (ga < M) regA[i] = *(const float4*)(A + (size_t)ga * K + k0 + c4 * 4);
            else        regA[i] = make_float4(0.f, 0.f, 0.f, 0.f);
            int gb = col0_blk + r;  // N is always a multiple of 128 here
            regB[i] = *(const float4*)(B + (size_t)gb * K + k0 + c4 * 4);
        }
    };

    auto STS = [&](int buf) {
        float* dA = sA + buf * BM * SROW;
        float* dB = sB + buf * BN * SROW;
        #pragma unroll
        for (int i = 0; i < 4; i++) {
            int id = t + i * 256;
            int r  = id >> 3;
            int c4 = id & 7;
            uint4 ua;
            ua.x = f2tf32(regA[i].x); ua.y = f2tf32(regA[i].y);
            ua.z = f2tf32(regA[i].z); ua.w = f2tf32(regA[i].w);
            *(uint4*)(dA + r * SROW + c4 * 4) = ua;
            uint4 ub;
            ub.x = f2tf32(regB[i].x); ub.y = f2tf32(regB[i].y);
            ub.z = f2tf32(regB[i].z); ub.w = f2tf32(regB[i].w);
            *(uint4*)(dB + r * SROW + c4 * 4) = ub;
        }
    };

    LDG(0);
    STS(0);
    __syncthreads();

    int buf = 0;
    for (int kt = 0; kt < KT; ++kt) {
        if (kt + 1 < KT) LDG(kt + 1);

        const uint32_t* uA = (const uint32_t*)(sA + buf * BM * SROW);
        const uint32_t* uB = (const uint32_t*)(sB + buf * BN * SROW);

        #pragma unroll
        for (int ks = 0; ks < 4; ++ks) {
            const int kk = ks * 8;
            uint32_t af[4][4], bf[4][2];
            #pragma unroll
            for (int mt = 0; mt < 4; ++mt) {
                int r = wm * 64 + mt * 16 + g;
                af[mt][0] = uA[(r    ) * SROW + kk + tg    ];
                af[mt][1] = uA[(r + 8) * SROW + kk + tg    ];
                af[mt][2] = uA[(r    ) * SROW + kk + tg + 4];
                af[mt][3] = uA[(r + 8) * SROW + kk + tg + 4];
            }
            #pragma unroll
            for (int nt = 0; nt < 4; ++nt) {
                int n = wn * 32 + nt * 8 + g;
                bf[nt][0] = uB[n * SROW + kk + tg    ];
                bf[nt][1] = uB[n * SROW + kk + tg + 4];
            }
            #pragma unroll
            for (int mt = 0; mt < 4; ++mt)
                #pragma unroll
                for (int nt = 0; nt < 4; ++nt)
                    mma_tf32(acc[mt][nt], af[mt], bf[nt]);
        }

        if (kt + 1 < KT) STS(buf ^ 1);
        __syncthreads();
        buf ^= 1;
    }

    // Epilogue: add bias, guarded row writes
    #pragma unroll
    for (int mt = 0; mt < 4; ++mt) {
        int r0 = row0_blk + wm * 64 + mt * 16 + g;
        #pragma unroll
        for (int nt = 0; nt < 4; ++nt) {
            int c0 = col0_blk + wn * 32 + nt * 8 + tg * 2;
            float b0v = bias[c0];
            float b1v = bias[c0 + 1];
            if (r0 < M) {
                C[(size_t)r0 * N + c0    ] = acc[mt][nt][0] + b0v;
                C[(size_t)r0 * N + c0 + 1] = acc[mt][nt][1] + b1v;
            }
            if (r0 + 8 < M) {
                C[(size_t)(r0 + 8) * N + c0    ] = acc[mt][nt][2] + b0v;
                C[(size_t)(r0 + 8) * N + c0 + 1] = acc[mt][nt][3] + b1v;
            }
        }
    }
}

// ---------------------------------------------------------------------------
// RMSNorm in-place over rows of length DIMM (5120). One block of 256 per row.
// ---------------------------------------------------------------------------
__global__ void __launch_bounds__(256)
rmsnorm_kernel(float* __restrict__ buf, const float* __restrict__ gvec)
{
    const int row = blockIdx.x;
    const int t = threadIdx.x;
    const int lane = t & 31;
    const int warp = t >> 5;

    float4* p4 = (float4*)(buf + (size_t)row * DIMM);
    const float4* g4 = (const float4*)gvec;

    float4 v[5];
    float ss = 0.f;
    #pragma unroll
    for (int i = 0; i < 5; i++) {
        v[i] = p4[t + i * 256];
        ss += v[i].x * v[i].x + v[i].y * v[i].y + v[i].z * v[i].z + v[i].w * v[i].w;
    }

    #pragma unroll
    for (int off = 16; off > 0; off >>= 1)
        ss += __shfl_xor_sync(0xffffffffu, ss, off);

    __shared__ float red[8];
    __shared__ float stot;
    if (lane == 0) red[warp] = ss;
    __syncthreads();
    if (t < 8) {
        float tot = red[t];
        #pragma unroll
        for (int off = 4; off > 0; off >>= 1)
            tot += __shfl_xor_sync(0x000000ffu, tot, off);
        if (t == 0) stot = tot;
    }
    __syncthreads();

    const float inv = rsqrtf(stot / (float)DIMM + 1e-6f);

    #pragma unroll
    for (int i = 0; i < 5; i++) {
        float4 gv = g4[t + i * 256];
        float4 o;
        o.x = v[i].x * inv * gv.x;
        o.y = v[i].y * inv * gv.y;
        o.z = v[i].z * inv * gv.z;
        o.w = v[i].w * inv * gv.w;
        p4[t + i * 256] = o;
    }
}

// ---------------------------------------------------------------------------
// Attention: per (frame, head): softmax(Q Kᵀ * scale) V, 16 keys per frame.
// grid.x = frame*NHEADS + head, grid.y = chunk of 16 q-rows; 128 threads.
// ---------------------------------------------------------------------------
#define SKPAD 132

__global__ void __launch_bounds__(128)
attn_kernel(const float* __restrict__ q, const float* __restrict__ k,
            const float* __restrict__ v, float* __restrict__ o)
{
    const int fh = blockIdx.x;
    const int f  = fh / NHEADS;
    const int h  = fh % NHEADS;

    __shared__ float sk[16][SKPAD];
    __shared__ float sv[16][SKPAD];

    const int t = threadIdx.x;
    #pragma unroll
    for (int i = 0; i < 4; i++) {
        int id = t + i * 128;   // float4 id within 16x128
        int j  = id >> 5;       // key row 0..15
        int c4 = id & 31;       // float4 col
        size_t goff = ((size_t)(f * 16 + j)) * DIMM + h * HDIM + c4 * 4;
        float4 kv = *(const float4*)(k + goff);
        *(float4*)(&sk[j][c4 * 4]) = kv;
        float4 vv = *(const float4*)(v + goff);
        *(float4*)(&sv[j][c4 * 4]) = vv;
    }
    __syncthreads();

    const int warp = t >> 5;
    const int lane = t & 31;
    const float scale = 0.08838834764831844f;  // 1/sqrt(128)

    #pragma unroll
    for (int rr = 0; rr < 4; ++rr) {
        const int pos = blockIdx.y * 16 + warp * 4 + rr;
        if (pos >= HWTOK) break;  // uniform across warp

        const float4* q4 = (const float4*)(q + ((size_t)(f * HWTOK + pos)) * DIMM + h * HDIM);

        float logit = -1e30f;
        if (lane < 16) {
            float s = 0.f;
            #pragma unroll
            for (int c = 0; c < 32; c++) {
                float4 a = q4[c];
                float4 b = *(const float4*)(&sk[lane][c * 4]);
                s += a.x * b.x + a.y * b.y + a.z * b.z + a.w * b.w;
            }
            logit = s * scale;
        }

        // softmax over 16 lanes
        float m = logit;
        #pragma unroll
        for (int off = 8; off > 0; off >>= 1)
            m = fmaxf(m, __shfl_xor_sync(0xffffffffu, m, off, 16));
        float e = (lane < 16) ? expf(logit - m) : 0.f;
        float ssum = e;
        #pragma unroll
        for (int off = 8; off > 0; off >>= 1)
            ssum += __shfl_xor_sync(0xffffffffu, ssum, off, 16);
        float att = (lane < 16) ? (e / ssum) : 0.f;

        // o[d] = sum_j att_j * v[j][d]; lane owns 4 consecutive d's
        float4 oacc = make_float4(0.f, 0.f, 0.f, 0.f);
        #pragma unroll
        for (int j = 0; j < 16; j++) {
            float aj = __shfl_sync(0xffffffffu, att, j);
            float4 vv = *(const float4*)(&sv[j][lane * 4]);
            oacc.x += aj * vv.x;
            oacc.y += aj * vv.y;
            oacc.z += aj * vv.z;
            oacc.w += aj * vv.w;
        }
        *(float4*)(o + ((size_t)(f * HWTOK + pos)) * DIMM + h * HDIM + lane * 4) = oacc;
    }
}

// ---------------------------------------------------------------------------
// Launcher
// ---------------------------------------------------------------------------
extern "C" void kernel_launch(void* const* d_in, const int* in_sizes, int n_in,
                              void* d_out, int out_size)
{
    const float* x   = (const float*)d_in[0];
    const float* ctx = (const float*)d_in[1];
    // d_in[2..5]: context_lens, grid_sizes, freqs, audio_seq_len (unused; shapes fixed)
    const float* Wq  = (const float*)d_in[6];
    const float* bq  = (const float*)d_in[7];
    const float* Wk  = (const float*)d_in[8];
    const float* bk  = (const float*)d_in[9];
    const float* Wv  = (const float*)d_in[10];
    const float* bv  = (const float*)d_in[11];
    const float* Wo  = (const float*)d_in[12];
    const float* bo  = (const float*)d_in[13];
    const float* gq  = (const float*)d_in[14];
    const float* gk  = (const float*)d_in[15];
    float* out = (float*)d_out;

    float *qb, *kb, *vb, *ob;
    cudaGetSymbolAddress((void**)&qb, g_q);
    cudaGetSymbolAddress((void**)&kb, g_k);
    cudaGetSymbolAddress((void**)&vb, g_v);
    cudaGetSymbolAddress((void**)&ob, g_o);

    const int smem_bytes = 2 * (BM * SROW + BN * SROW) * (int)sizeof(float); // 73728
    cudaFuncSetAttribute(gemm_tf32_kernel, cudaFuncAttributeMaxDynamicSharedMemorySize, smem_bytes);

    dim3 blk(256);

    // Q projection: 9360x5120 = x @ Wq^T + bq
    {
        dim3 grid(DIMM / BN, (L1TOK + BM - 1) / BM);
        gemm_tf32_kernel<<<grid, blk, smem_bytes>>>(x, Wq, bq, qb, L1TOK, DIMM, DIMM);
    }
    // K projection: 96x5120 = ctx @ Wk^T + bk
    {
        dim3 grid(DIMM / BN, 1);
        gemm_tf32_kernel<<<grid, blk, smem_bytes>>>(ctx, Wk, bk, kb, LATOK, DIMM, KVD);
    }
    // V projection: 96x5120 = ctx @ Wv^T + bv
    {
        dim3 grid(DIMM / BN, 1);
        gemm_tf32_kernel<<<grid, blk, smem_bytes>>>(ctx, Wv, bv, vb, LATOK, DIMM, KVD);
    }

    // RMSNorm q and k (in place)
    rmsnorm_kernel<<<L1TOK, 256>>>(qb, gq);
    rmsnorm_kernel<<<LATOK, 256>>>(kb, gk);

    // Attention
    {
        dim3 grid(NFRAMES * NHEADS, (HWTOK + 15) / 16);
        attn_kernel<<<grid, 128>>>(qb, kb, vb, ob);
    }

    // Output projection: out = o @ Wo^T + bo
    {
        dim3 grid(DIMM / BN, (L1TOK + BM - 1) / BM);
        gemm_tf32_kernel<<<grid, blk, smem_bytes>>>(ob, Wo, bo, out, L1TOK, DIMM, DIMM);
    }
}

// round 5
// speedup vs baseline: 1.0991x; 1.0987x over previous
#include <cuda_runtime.h>
#include <cstdint>

// Problem constants (fixed by setup_inputs)
#define L1TOK   9360
#define DIMM    5120
#define KVD     1536
#define NHEADS  40
#define HDIM    128
#define LATOK   96
#define NFRAMES 6
#define HWTOK   1560

// Scratch (device globals: allocation-free)
__device__ float g_x [(size_t)L1TOK * DIMM];   // tf32-rounded x
__device__ float g_wq[(size_t)DIMM  * DIMM];   // tf32-rounded Wq
__device__ float g_wo[(size_t)DIMM  * DIMM];   // tf32-rounded Wo
__device__ float g_q [(size_t)L1TOK * DIMM];
__device__ float g_k [(size_t)LATOK * DIMM];
__device__ float g_v [(size_t)LATOK * DIMM];
__device__ float g_o [(size_t)L1TOK * DIMM];   // tf32-rounded attention output

// ---------------------------------------------------------------------------
// Helpers
// ---------------------------------------------------------------------------
__device__ __forceinline__ uint32_t f2tf32(float x) {
    uint32_t u;
    asm("cvt.rna.tf32.f32 %0, %1;" : "=r"(u) : "f"(x));
    return u;
}
__device__ __forceinline__ uint32_t smem_u32(const void* p) {
    uint32_t a;
    asm("{ .reg .u64 t; cvta.to.shared.u64 t, %1; cvt.u32.u64 %0, t; }" : "=r"(a) : "l"(p));
    return a;
}
__device__ __forceinline__ void mma_tf32(float* c, const uint32_t* a, uint32_t b0, uint32_t b1) {
    asm volatile(
        "mma.sync.aligned.m16n8k8.row.col.f32.tf32.tf32.f32 "
        "{%0,%1,%2,%3}, {%4,%5,%6,%7}, {%8,%9}, {%0,%1,%2,%3};\n"
        : "+f"(c[0]), "+f"(c[1]), "+f"(c[2]), "+f"(c[3])
        : "r"(a[0]), "r"(a[1]), "r"(a[2]), "r"(a[3]), "r"(b0), "r"(b1));
}
__device__ __forceinline__ void cp16(uint32_t dst, const float* src, bool pred) {
    asm volatile("cp.async.ca.shared.global [%0], [%1], 16, %2;"
                 :: "r"(dst), "l"(src), "r"(pred ? 16 : 0));
}
__device__ __forceinline__ void cp_commit() {
    asm volatile("cp.async.commit_group;" ::: "memory");
}
__device__ __forceinline__ void cp_wait2() {
    asm volatile("cp.async.wait_group 2;" ::: "memory");
}

// ---------------------------------------------------------------------------
// Big GEMM: C[M,5120] = A[M,5120] @ B[5120,5120]^T + bias
// A, B must be PRE-ROUNDED to tf32 values (stored as fp32).
// CTA tile: 256(M) x 128(N), BK=16, 4-stage cp.async pipeline, 256 threads.
// 8 warps in 4(m) x 2(n), warp tile 64x64.
// Stage layout: A 256 rows x 20 floats (pad), B 128 rows x 20 floats.
// ---------------------------------------------------------------------------
#define BKQ 16
#define SROWF 20                      // padded row stride (floats)
#define STG_A_F (256 * SROWF)         // 5120 floats
#define STG_B_F (128 * SROWF)         // 2560 floats
#define STG_F   (STG_A_F + STG_B_F)   // 7680 floats = 30720 B
#define NSTG 4
#define GSMEM (NSTG * STG_F * 4)      // 122880 B
#define KTQ (DIMM / BKQ)              // 320

__global__ void __launch_bounds__(256, 1)
gemm_tc_kernel(const float* __restrict__ A, const float* __restrict__ B,
               const float* __restrict__ bias, float* __restrict__ C, int M)
{
    extern __shared__ float smp[];
    const uint32_t sbase = smem_u32(smp);
    const int t    = threadIdx.x;
    const int warp = t >> 5;
    const int lane = t & 31;
    const int wm   = warp >> 1;      // 0..3  (64 rows)
    const int wn   = warp & 1;       // 0..1  (64 cols)
    const int g    = lane >> 2;
    const int tg   = lane & 3;
    const int n0   = blockIdx.x * 128;
    const int m0   = blockIdx.y * 256;

    float acc[4][8][4];
    #pragma unroll
    for (int i = 0; i < 4; i++)
        #pragma unroll
        for (int j = 0; j < 8; j++)
            #pragma unroll
            for (int r = 0; r < 4; r++) acc[i][j][r] = 0.f;

    // --- stage fill: 6 cp.async 16B per thread ---
    auto fill = [&](int stage, int kt) {
        const int k0 = kt * BKQ;
        const uint32_t sb = sbase + stage * (STG_F * 4);
        #pragma unroll
        for (int i = 0; i < 4; i++) {           // A: 1024 chunks
            int id  = t + i * 256;
            int row = id >> 2, c4 = id & 3;
            cp16(sb + row * 80 + c4 * 16,
                 A + (size_t)(m0 + row) * DIMM + k0 + c4 * 4,
                 (m0 + row) < M);
        }
        #pragma unroll
        for (int i = 0; i < 2; i++) {           // B: 512 chunks
            int id  = t + i * 256;
            int row = id >> 2, c4 = id & 3;
            cp16(sb + STG_A_F * 4 + row * 80 + c4 * 16,
                 B + (size_t)(n0 + row) * DIMM + k0 + c4 * 4, true);
        }
    };

    // prologue: stages 0..2
    #pragma unroll
    for (int s = 0; s < 3; s++) { fill(s, s); cp_commit(); }

    const int aoff0 = (wm * 64 + g) * SROWF + tg;
    const int boff0 = STG_A_F + (wn * 64 + g) * SROWF + tg;

    for (int kt = 0; kt < KTQ; ++kt) {
        cp_wait2();
        __syncthreads();

        const int buf = kt & 3;
        if (kt + 3 < KTQ) fill((kt + 3) & 3, kt + 3);
        cp_commit();

        const uint32_t* st = (const uint32_t*)(smp + buf * STG_F);
        #pragma unroll
        for (int ks = 0; ks < 2; ++ks) {
            const int kk = ks * 8;
            uint32_t af[4][4];
            #pragma unroll
            for (int mt = 0; mt < 4; ++mt) {
                const int ao = aoff0 + mt * (16 * SROWF) + kk;
                af[mt][0] = st[ao];
                af[mt][1] = st[ao + 8 * SROWF];
                af[mt][2] = st[ao + 4];
                af[mt][3] = st[ao + 8 * SROWF + 4];
            }
            #pragma unroll
            for (int nt = 0; nt < 8; ++nt) {
                const int bo = boff0 + nt * (8 * SROWF) + kk;
                uint32_t b0 = st[bo];
                uint32_t b1 = st[bo + 4];
                #pragma unroll
                for (int mt = 0; mt < 4; ++mt)
                    mma_tf32(acc[mt][nt], af[mt], b0, b1);
            }
        }
        __syncthreads();
    }

    // --- epilogue ---
    #pragma unroll
    for (int mt = 0; mt < 4; ++mt) {
        const int r0 = m0 + wm * 64 + mt * 16 + g;
        #pragma unroll
        for (int nt = 0; nt < 8; ++nt) {
            const int c0 = n0 + wn * 64 + nt * 8 + tg * 2;
            const float b0v = bias[c0];
            const float b1v = bias[c0 + 1];
            if (r0 < M) {
                float2 o0 = { acc[mt][nt][0] + b0v, acc[mt][nt][1] + b1v };
                *(float2*)(C + (size_t)r0 * DIMM + c0) = o0;
            }
            if (r0 + 8 < M) {
                float2 o1 = { acc[mt][nt][2] + b0v, acc[mt][nt][3] + b1v };
                *(float2*)(C + (size_t)(r0 + 8) * DIMM + c0) = o1;
            }
        }
    }
}

// ---------------------------------------------------------------------------
// Pre-round kernel: dst = tf32_rna(src), vectorized
// ---------------------------------------------------------------------------
__global__ void __launch_bounds__(256)
round_kernel(float* __restrict__ dst, const float* __restrict__ src, int n4)
{
    const int stride = gridDim.x * 256;
    for (int i = blockIdx.x * 256 + threadIdx.x; i < n4; i += stride) {
        float4 v = ((const float4*)src)[i];
        uint4 u = { f2tf32(v.x), f2tf32(v.y), f2tf32(v.z), f2tf32(v.w) };
        ((uint4*)dst)[i] = u;
    }
}

// ---------------------------------------------------------------------------
// Legacy TF32 GEMM for small K/V projections (M=96): C = A @ B^T + bias
// ---------------------------------------------------------------------------
__device__ __forceinline__ void mma_tf32b(float* c, const uint32_t* a, const uint32_t* b) {
    asm volatile(
        "mma.sync.aligned.m16n8k8.row.col.f32.tf32.tf32.f32 "
        "{%0,%1,%2,%3}, {%4,%5,%6,%7}, {%8,%9}, {%0,%1,%2,%3};\n"
        : "+f"(c[0]), "+f"(c[1]), "+f"(c[2]), "+f"(c[3])
        : "r"(a[0]), "r"(a[1]), "r"(a[2]), "r"(a[3]), "r"(b[0]), "r"(b[1]));
}
#define BM 128
#define BN 128
#define SROW 36

__global__ void __launch_bounds__(256, 1)
gemm_tf32_kernel(const float* __restrict__ A, const float* __restrict__ B,
                 const float* __restrict__ bias, float* __restrict__ C,
                 int M, int N, int K)
{
    extern __shared__ float fsm[];
    float* sA = fsm;
    float* sB = fsm + 2 * BM * SROW;
    const int t = threadIdx.x, warp = t >> 5, lane = t & 31;
    const int wm = warp >> 2, wn = warp & 3, g = lane >> 2, tg = lane & 3;
    const int row0 = blockIdx.y * BM, col0 = blockIdx.x * BN;

    float acc[4][4][4];
    #pragma unroll
    for (int i = 0; i < 4; i++) for (int j = 0; j < 4; j++) for (int r = 0; r < 4; r++) acc[i][j][r] = 0.f;
    float4 rA[4], rB[4];
    const int KTl = K / 32;

    auto LDG = [&](int kt) {
        const int k0 = kt * 32;
        #pragma unroll
        for (int i = 0; i < 4; i++) {
            int id = t + i * 256, r = id >> 3, c4 = id & 7;
            int ga = row0 + r;
            rA[i] = (ga < M) ? *(const float4*)(A + (size_t)ga * K + k0 + c4 * 4) : make_float4(0.f,0.f,0.f,0.f);
            rB[i] = *(const float4*)(B + (size_t)(col0 + r) * K + k0 + c4 * 4);
        }
    };
    auto STS = [&](int buf) {
        float* dA = sA + buf * BM * SROW;
        float* dB = sB + buf * BN * SROW;
        #pragma unroll
        for (int i = 0; i < 4; i++) {
            int id = t + i * 256, r = id >> 3, c4 = id & 7;
            uint4 ua = { f2tf32(rA[i].x), f2tf32(rA[i].y), f2tf32(rA[i].z), f2tf32(rA[i].w) };
            *(uint4*)(dA + r * SROW + c4 * 4) = ua;
            uint4 ub = { f2tf32(rB[i].x), f2tf32(rB[i].y), f2tf32(rB[i].z), f2tf32(rB[i].w) };
            *(uint4*)(dB + r * SROW + c4 * 4) = ub;
        }
    };

    LDG(0); STS(0); __syncthreads();
    int buf = 0;
    for (int kt = 0; kt < KTl; ++kt) {
        if (kt + 1 < KTl) LDG(kt + 1);
        const uint32_t* uA = (const uint32_t*)(sA + buf * BM * SROW);
        const uint32_t* uB = (const uint32_t*)(sB + buf * BN * SROW);
        #pragma unroll
        for (int ks = 0; ks < 4; ++ks) {
            const int kk = ks * 8;
            uint32_t af[4][4], bf[4][2];
            #pragma unroll
            for (int mt = 0; mt < 4; ++mt) {
                int r = wm * 64 + mt * 16 + g;
                af[mt][0] = uA[r * SROW + kk + tg];
                af[mt][1] = uA[(r + 8) * SROW + kk + tg];
                af[mt][2] = uA[r * SROW + kk + tg + 4];
                af[mt][3] = uA[(r + 8) * SROW + kk + tg + 4];
            }
            #pragma unroll
            for (int nt = 0; nt < 4; ++nt) {
                int n = wn * 32 + nt * 8 + g;
                bf[nt][0] = uB[n * SROW + kk + tg];
                bf[nt][1] = uB[n * SROW + kk + tg + 4];
            }
            #pragma unroll
            for (int mt = 0; mt < 4; ++mt)
                #pragma unroll
                for (int nt = 0; nt < 4; ++nt)
                    mma_tf32b(acc[mt][nt], af[mt], bf[nt]);
        }
        if (kt + 1 < KTl) STS(buf ^ 1);
        __syncthreads();
        buf ^= 1;
    }
    #pragma unroll
    for (int mt = 0; mt < 4; ++mt) {
        int r0 = row0 + wm * 64 + mt * 16 + g;
        #pragma unroll
        for (int nt = 0; nt < 4; ++nt) {
            int c0 = col0 + wn * 32 + nt * 8 + tg * 2;
            float b0v = bias[c0], b1v = bias[c0 + 1];
            if (r0 < M) {
                C[(size_t)r0 * N + c0]     = acc[mt][nt][0] + b0v;
                C[(size_t)r0 * N + c0 + 1] = acc[mt][nt][1] + b1v;
            }
            if (r0 + 8 < M) {
                C[(size_t)(r0 + 8) * N + c0]     = acc[mt][nt][2] + b0v;
                C[(size_t)(r0 + 8) * N + c0 + 1] = acc[mt][nt][3] + b1v;
            }
        }
    }
}

// ---------------------------------------------------------------------------
// RMSNorm (rows of 5120)
// ---------------------------------------------------------------------------
__global__ void __launch_bounds__(256)
rmsnorm_kernel(float* __restrict__ buf, const float* __restrict__ gvec)
{
    const int row = blockIdx.x, t = threadIdx.x, lane = t & 31, warp = t >> 5;
    float4* p4 = (float4*)(buf + (size_t)row * DIMM);
    const float4* g4 = (const float4*)gvec;
    float4 v[5]; float ss = 0.f;
    #pragma unroll
    for (int i = 0; i < 5; i++) {
        v[i] = p4[t + i * 256];
        ss += v[i].x*v[i].x + v[i].y*v[i].y + v[i].z*v[i].z + v[i].w*v[i].w;
    }
    #pragma unroll
    for (int off = 16; off > 0; off >>= 1) ss += __shfl_xor_sync(0xffffffffu, ss, off);
    __shared__ float red[8]; __shared__ float stot;
    if (lane == 0) red[warp] = ss;
    __syncthreads();
    if (t < 8) {
        float tot = red[t];
        #pragma unroll
        for (int off = 4; off > 0; off >>= 1) tot += __shfl_xor_sync(0xffu, tot, off);
        if (t == 0) stot = tot;
    }
    __syncthreads();
    const float inv = rsqrtf(stot / (float)DIMM + 1e-6f);
    #pragma unroll
    for (int i = 0; i < 5; i++) {
        float4 gv = g4[t + i * 256];
        float4 o = { v[i].x*inv*gv.x, v[i].y*inv*gv.y, v[i].z*inv*gv.z, v[i].w*inv*gv.w };
        p4[t + i * 256] = o;
    }
}

// ---------------------------------------------------------------------------
// Attention: per (frame, head), 16 keys. Output written tf32-rounded.
// ---------------------------------------------------------------------------
#define SKPAD 132
__global__ void __launch_bounds__(128)
attn_kernel(const float* __restrict__ q, const float* __restrict__ k,
            const float* __restrict__ v, float* __restrict__ o)
{
    const int fh = blockIdx.x, f = fh / NHEADS, h = fh % NHEADS;
    __shared__ float sk[16][SKPAD];
    __shared__ float sv[16][SKPAD];
    const int t = threadIdx.x;
    #pragma unroll
    for (int i = 0; i < 4; i++) {
        int id = t + i * 128, j = id >> 5, c4 = id & 31;
        size_t goff = ((size_t)(f * 16 + j)) * DIMM + h * HDIM + c4 * 4;
        *(float4*)(&sk[j][c4 * 4]) = *(const float4*)(k + goff);
        *(float4*)(&sv[j][c4 * 4]) = *(const float4*)(v + goff);
    }
    __syncthreads();
    const int warp = t >> 5, lane = t & 31;
    const float scale = 0.08838834764831844f;
    #pragma unroll
    for (int rr = 0; rr < 4; ++rr) {
        const int pos = blockIdx.y * 16 + warp * 4 + rr;
        if (pos >= HWTOK) break;
        const float4* q4 = (const float4*)(q + ((size_t)(f * HWTOK + pos)) * DIMM + h * HDIM);
        float logit = -1e30f;
        if (lane < 16) {
            float s = 0.f;
            #pragma unroll
            for (int c = 0; c < 32; c++) {
                float4 a = q4[c];
                float4 b = *(const float4*)(&sk[lane][c * 4]);
                s += a.x*b.x + a.y*b.y + a.z*b.z + a.w*b.w;
            }
            logit = s * scale;
        }
        float m = logit;
        #pragma unroll
        for (int off = 8; off > 0; off >>= 1) m = fmaxf(m, __shfl_xor_sync(0xffffffffu, m, off, 16));
        float e = (lane < 16) ? expf(logit - m) : 0.f;
        float ssum = e;
        #pragma unroll
        for (int off = 8; off > 0; off >>= 1) ssum += __shfl_xor_sync(0xffffffffu, ssum, off, 16);
        float att = (lane < 16) ? (e / ssum) : 0.f;
        float4 oacc = make_float4(0.f, 0.f, 0.f, 0.f);
        #pragma unroll
        for (int j = 0; j < 16; j++) {
            float aj = __shfl_sync(0xffffffffu, att, j);
            float4 vv = *(const float4*)(&sv[j][lane * 4]);
            oacc.x += aj*vv.x; oacc.y += aj*vv.y; oacc.z += aj*vv.z; oacc.w += aj*vv.w;
        }
        // store tf32-rounded so the O-projection GEMM can consume it directly
        uint4 u = { f2tf32(oacc.x), f2tf32(oacc.y), f2tf32(oacc.z), f2tf32(oacc.w) };
        *(uint4*)(o + ((size_t)(f * HWTOK + pos)) * DIMM + h * HDIM + lane * 4) = u;
    }
}

// ---------------------------------------------------------------------------
// Launcher
// ---------------------------------------------------------------------------
extern "C" void kernel_launch(void* const* d_in, const int* in_sizes, int n_in,
                              void* d_out, int out_size)
{
    const float* x   = (const float*)d_in[0];
    const float* ctx = (const float*)d_in[1];
    const float* Wq  = (const float*)d_in[6];
    const float* bq  = (const float*)d_in[7];
    const float* Wk  = (const float*)d_in[8];
    const float* bk  = (const float*)d_in[9];
    const float* Wv  = (const float*)d_in[10];
    const float* bv  = (const float*)d_in[11];
    const float* Wo  = (const float*)d_in[12];
    const float* bo  = (const float*)d_in[13];
    const float* gq  = (const float*)d_in[14];
    const float* gk  = (const float*)d_in[15];
    float* out = (float*)d_out;

    float *xb, *wqb, *wob, *qb, *kb, *vb, *ob;
    cudaGetSymbolAddress((void**)&xb,  g_x);
    cudaGetSymbolAddress((void**)&wqb, g_wq);
    cudaGetSymbolAddress((void**)&wob, g_wo);
    cudaGetSymbolAddress((void**)&qb,  g_q);
    cudaGetSymbolAddress((void**)&kb,  g_k);
    cudaGetSymbolAddress((void**)&vb,  g_v);
    cudaGetSymbolAddress((void**)&ob,  g_o);

    cudaFuncSetAttribute(gemm_tc_kernel, cudaFuncAttributeMaxDynamicSharedMemorySize, GSMEM);
    const int lsmem = 2 * (BM * SROW + BN * SROW) * (int)sizeof(float);
    cudaFuncSetAttribute(gemm_tf32_kernel, cudaFuncAttributeMaxDynamicSharedMemorySize, lsmem);

    // Pre-round inputs that feed the big GEMMs
    round_kernel<<<2048, 256>>>(xb,  x,  (int)((size_t)L1TOK * DIMM / 4));
    round_kernel<<<2048, 256>>>(wqb, Wq, (int)((size_t)DIMM  * DIMM / 4));
    round_kernel<<<2048, 256>>>(wob, Wo, (int)((size_t)DIMM  * DIMM / 4));

    // Q projection: g_q = x @ Wq^T + bq   (grid: x = N tiles, y = M tiles)
    {
        dim3 grid(DIMM / 128, (L1TOK + 255) / 256);
        gemm_tc_kernel<<<grid, 256, GSMEM>>>(xb, wqb, bq, qb, L1TOK);
    }
    // K / V projections (tiny)
    {
        dim3 grid(DIMM / BN, 1);
        gemm_tf32_kernel<<<grid, 256, lsmem>>>(ctx, Wk, bk, kb, LATOK, DIMM, KVD);
        gemm_tf32_kernel<<<grid, 256, lsmem>>>(ctx, Wv, bv, vb, LATOK, DIMM, KVD);
    }
    // RMSNorm
    rmsnorm_kernel<<<L1TOK, 256>>>(qb, gq);
    rmsnorm_kernel<<<LATOK, 256>>>(kb, gk);
    // Attention (writes tf32-rounded o)
    {
        dim3 grid(NFRAMES * NHEADS, (HWTOK + 15) / 16);
        attn_kernel<<<grid, 128>>>(qb, kb, vb, ob);
    }
    // Output projection: out = o @ Wo^T + bo
    {
        dim3 grid(DIMM / 128, (L1TOK + 255) / 256);
        gemm_tc_kernel<<<grid, 256, GSMEM>>>(ob, wob, bo, out, L1TOK);
    }
}